// round 10
// baseline (speedup 1.0000x reference)
#include <cuda_runtime.h>
#include <cstdint>
#include <math.h>

// Problem constants
#define NBINS (1 << 21)          // 128^3
#define NPIX  (4096 * 4096)      // 16,777,216 pixels
#define NFLAGW (NBINS / 32)      // 65536 flag words
#define NCHUNK (NBINS / 32)      // 65536 32-bin chunks
#define FGRID  148               // fused kernel: one block per SM (co-resident)
#define FWARPS (FGRID * 32)      // 4736 warps
#define CPT    14                // ceil(65536 / 4736) chunks per warp

// Fixed-point mask accumulation: 24 fractional bits, count in bits [40:64)
#define MASK_SCALE 16777216.0f        // 2^24
#define MASK_INV_SCALE (1.0f / 16777216.0f)
#define MASK_INV_SCALE_D (1.0 / 16777216.0)
#define COUNT_SHIFT 40
#define MASK40 0xFFFFFFFFFFULL        // low 40 bits

// k_out smem bit-table: 28672 words = 112 KB -> 2 blocks/SM (100% occupancy).
// Covers bins < 917,504 (43.75%); the rest hits the 256KB L2-resident g_flag.
#define SMEM_WORDS 28672
#define SMEM_BYTES (SMEM_WORDS * 4)
#define OUT_GRID (148 * 2)

// Scratch (allocation-free rule: __device__ globals)
__device__ unsigned long long g_hist[NBINS];   // 16 MB, packed count|mask
__device__ int                g_bins[NPIX];    // 64 MB per-pixel bin index
__device__ unsigned int       g_flag[NFLAGW];  // 256 KB bit table
__device__ double             g_sumf_in, g_suml_in, g_avg;
__device__ unsigned long long g_mask_total;
__device__ unsigned int       g_bar1, g_bar2;  // software grid barriers

// ---------------------------------------------------------------------------
// K0: clear histogram (vectorized) + scalars + barrier counters
// ---------------------------------------------------------------------------
__global__ void k_clear() {
    int i = blockIdx.x * blockDim.x + threadIdx.x;
    if (i < NBINS / 2) ((ulonglong2*)g_hist)[i] = make_ulonglong2(0ULL, 0ULL);
    if (i == 0) {
        g_sumf_in = 0.0; g_suml_in = 0.0; g_avg = 0.0;
        g_mask_total = 0ULL;
        g_bar1 = 0u; g_bar2 = 0u;
    }
}

// ---------------------------------------------------------------------------
// K1: histogram accumulate + per-pixel bin store. 4 pixels per thread.
// (exact R5/R8 version — proven best; atomic-issue floor, do not touch)
// ---------------------------------------------------------------------------
__global__ void __launch_bounds__(256) k_hist(const int* __restrict__ img,
                                              const float* __restrict__ mask) {
    int t = blockIdx.x * blockDim.x + threadIdx.x;   // 0 .. NPIX/4-1
    if (t >= NPIX / 4) return;

    const int4* img4 = (const int4*)img;
    int4 a = img4[t * 3 + 0];
    int4 b = img4[t * 3 + 1];
    int4 c = img4[t * 3 + 2];
    float4 m = ((const float4*)mask)[t];

    int bin0 = ((a.x >> 1) << 14) | ((a.y >> 1) << 7) | (a.z >> 1);
    int bin1 = ((a.w >> 1) << 14) | ((b.x >> 1) << 7) | (b.y >> 1);
    int bin2 = ((b.z >> 1) << 14) | ((b.w >> 1) << 7) | (c.x >> 1);
    int bin3 = ((c.y >> 1) << 14) | ((c.z >> 1) << 7) | (c.w >> 1);

    unsigned long long v0 = (1ULL << COUNT_SHIFT) | (unsigned long long)(m.x * MASK_SCALE + 0.5f);
    unsigned long long v1 = (1ULL << COUNT_SHIFT) | (unsigned long long)(m.y * MASK_SCALE + 0.5f);
    unsigned long long v2 = (1ULL << COUNT_SHIFT) | (unsigned long long)(m.z * MASK_SCALE + 0.5f);
    unsigned long long v3 = (1ULL << COUNT_SHIFT) | (unsigned long long)(m.w * MASK_SCALE + 0.5f);

    atomicAdd(&g_hist[bin0], v0);
    atomicAdd(&g_hist[bin1], v1);
    atomicAdd(&g_hist[bin2], v2);
    atomicAdd(&g_hist[bin3], v3);

    ((int4*)g_bins)[t] = make_int4(bin0, bin1, bin2, bin3);
}

// ---------------------------------------------------------------------------
// K2 (fused): sums + log-ratio + flag table in one persistent kernel.
// (exact R8 version — proven)
// ---------------------------------------------------------------------------
__device__ __forceinline__ void grid_barrier(unsigned int* bar) {
    __syncthreads();
    if (threadIdx.x == 0) {
        __threadfence();
        atomicAdd(bar, 1u);
        while (*((volatile unsigned int*)bar) < FGRID) { }
        __threadfence();
    }
    __syncthreads();
}

__global__ void __launch_bounds__(1024) k_fused(const float* __restrict__ full_in,
                                                const float* __restrict__ lines_in) {
    int tid  = threadIdx.x;
    int lane = tid & 31;
    int wid  = tid >> 5;
    int W    = blockIdx.x * 32 + wid;    // global warp id, 0..4735

    // ---------------- Phase A: sums ----------------
    unsigned long long msum = 0ULL;
    float fsum = 0.0f, lsum = 0.0f;
    #pragma unroll
    for (int j = 0; j < CPT; j++) {
        int c = W + j * FWARPS;
        if (c < NCHUNK) {                 // warp-uniform guard
            int bin = c * 32 + lane;
            unsigned long long h = g_hist[bin];
            msum += (h & MASK40);
            fsum += full_in[bin];
            lsum += lines_in[bin];
        }
    }
    for (int o = 16; o > 0; o >>= 1) {
        msum += __shfl_down_sync(0xFFFFFFFFu, msum, o);
        fsum += __shfl_down_sync(0xFFFFFFFFu, fsum, o);
        lsum += __shfl_down_sync(0xFFFFFFFFu, lsum, o);
    }
    __shared__ unsigned long long sm[32];
    __shared__ float sf[32], sl[32];
    if (lane == 0) { sm[wid] = msum; sf[wid] = fsum; sl[wid] = lsum; }
    __syncthreads();
    if (wid == 0) {
        msum = sm[lane]; fsum = sf[lane]; lsum = sl[lane];
        for (int o = 16; o > 0; o >>= 1) {
            msum += __shfl_down_sync(0xFFFFFFFFu, msum, o);
            fsum += __shfl_down_sync(0xFFFFFFFFu, fsum, o);
            lsum += __shfl_down_sync(0xFFFFFFFFu, lsum, o);
        }
        if (lane == 0) {
            atomicAdd(&g_mask_total, msum);
            atomicAdd(&g_sumf_in, (double)fsum);
            atomicAdd(&g_suml_in, (double)lsum);
        }
    }
    grid_barrier(&g_bar1);

    // Derive scalars (identical doubles in every block)
    __shared__ float sC, sInvSl;
    if (tid == 0) {
        double sfd = *((volatile double*)&g_sumf_in) + (double)NPIX + (double)NBINS;
        double sld = *((volatile double*)&g_suml_in)
                   + (double)(*((volatile unsigned long long*)&g_mask_total)) * MASK_INV_SCALE_D
                   + (double)NBINS * 1e-10;
        sC = (float)(log(sfd) - log(sld));
        sInvSl = (float)(1.0 / sld);
    }
    __syncthreads();
    float C = sC, inv_sl = sInvSl;

    // ---------------- Phase B: log ratios (register-resident) + avg ----------
    float lr[CPT];
    float avg = 0.0f;
    #pragma unroll
    for (int j = 0; j < CPT; j++) {
        int c = W + j * FWARPS;
        if (c < NCHUNK) {                 // L2-hot re-reads
            int bin = c * 32 + lane;
            unsigned long long h = g_hist[bin];
            float cnt = (float)(h >> COUNT_SHIFT);
            float ms  = (float)(h & MASK40) * MASK_INV_SCALE;
            float f = full_in[bin] + cnt + 1.0f;
            float l = lines_in[bin] + ms + 1e-10f;
            float v = logf(l / f) + C;
            lr[j] = v;
            avg += (l * inv_sl) * v;
        } else {
            lr[j] = 0.0f;
        }
    }
    for (int o = 16; o > 0; o >>= 1)
        avg += __shfl_down_sync(0xFFFFFFFFu, avg, o);
    __shared__ float sa[32];
    if (lane == 0) sa[wid] = avg;
    __syncthreads();
    if (wid == 0) {
        avg = sa[lane];
        for (int o = 16; o > 0; o >>= 1)
            avg += __shfl_down_sync(0xFFFFFFFFu, avg, o);
        if (lane == 0) atomicAdd(&g_avg, (double)avg);
    }
    grid_barrier(&g_bar2);

    // ---------------- Phase C: flag bits via ballot ----------------
    float avgf = (float)(*((volatile double*)&g_avg));
    #pragma unroll
    for (int j = 0; j < CPT; j++) {
        int c = W + j * FWARPS;
        if (c < NCHUNK) {                 // warp-uniform: full-warp ballot
            unsigned int m = __ballot_sync(0xFFFFFFFFu, lr[j] > avgf);
            if (lane == 0) g_flag[c] = m;
        }
    }
}

// ---------------------------------------------------------------------------
// K4: gather, 4 px/thread (proven R8 shape). 112 KB smem table -> 2 blocks/SM
// (64 warps, 100% occupancy) to hide LDS/LDG latency; uncovered bins hit the
// L2-resident 256KB g_flag.
// ---------------------------------------------------------------------------
__global__ void __launch_bounds__(1024, 2) k_out(float* __restrict__ out) {
    extern __shared__ unsigned int s_flag[];
    for (int i = threadIdx.x; i < SMEM_WORDS; i += 1024)
        s_flag[i] = g_flag[i];
    __syncthreads();

    int stride = gridDim.x * 1024;
    for (int t = blockIdx.x * 1024 + threadIdx.x; t < NPIX / 4; t += stride) {
        int4 bb = ((const int4*)g_bins)[t];
        float4 o;
        {
            int w = bb.x >> 5, bit = bb.x & 31;
            unsigned int word = (w < SMEM_WORDS) ? s_flag[w] : __ldg(&g_flag[w]);
            o.x = (float)((word >> bit) & 1u);
        }
        {
            int w = bb.y >> 5, bit = bb.y & 31;
            unsigned int word = (w < SMEM_WORDS) ? s_flag[w] : __ldg(&g_flag[w]);
            o.y = (float)((word >> bit) & 1u);
        }
        {
            int w = bb.z >> 5, bit = bb.z & 31;
            unsigned int word = (w < SMEM_WORDS) ? s_flag[w] : __ldg(&g_flag[w]);
            o.z = (float)((word >> bit) & 1u);
        }
        {
            int w = bb.w >> 5, bit = bb.w & 31;
            unsigned int word = (w < SMEM_WORDS) ? s_flag[w] : __ldg(&g_flag[w]);
            o.w = (float)((word >> bit) & 1u);
        }
        ((float4*)out)[t] = o;
    }
}

extern "C" void kernel_launch(void* const* d_in, const int* in_sizes, int n_in,
                              void* d_out, int out_size) {
    const int*   img      = (const int*)d_in[0];
    const float* mask     = (const float*)d_in[1];
    const float* full_in  = (const float*)d_in[2];
    const float* lines_in = (const float*)d_in[3];
    float* out            = (float*)d_out;

    // Idempotent opt-in for 112KB dynamic smem (non-stream call; capture-safe).
    cudaFuncSetAttribute(k_out, cudaFuncAttributeMaxDynamicSharedMemorySize, SMEM_BYTES);

    k_clear<<<(NBINS / 2) / 256, 256>>>();
    k_hist <<<(NPIX / 4) / 256, 256>>>(img, mask);
    k_fused<<<FGRID, 1024>>>(full_in, lines_in);
    k_out  <<<OUT_GRID, 1024, SMEM_BYTES>>>(out);
}

// round 11
// speedup vs baseline: 1.2450x; 1.2450x over previous
#include <cuda_runtime.h>
#include <cstdint>
#include <math.h>

// Problem constants
#define NBINS (1 << 21)          // 128^3
#define NPIX  (4096 * 4096)      // 16,777,216 pixels
#define NFLAGW (NBINS / 32)      // 65536 flag words
#define NCHUNK (NBINS / 32)      // 65536 32-bin chunks
#define FGRID  148               // fused kernel: one block per SM (co-resident)
#define FWARPS (FGRID * 32)      // 4736 warps
#define CPT    14                // ceil(65536 / 4736) chunks per warp

// Fixed-point mask accumulation: 24 fractional bits, count in bits [40:64)
#define MASK_SCALE 16777216.0f        // 2^24
#define MASK_INV_SCALE (1.0f / 16777216.0f)
#define MASK_INV_SCALE_D (1.0 / 16777216.0)
#define COUNT_SHIFT 40
#define MASK40 0xFFFFFFFFFFULL        // low 40 bits

// k_out smem bit-table: 57344 words = 224 KB, 1 block/SM (R8 proven config —
// smem hit-rate dominates occupancy for this gather; R10's 112KB/2-block
// variant regressed 38us -> 81us).
#define SMEM_WORDS 57344
#define SMEM_BYTES (SMEM_WORDS * 4)

// Scratch (allocation-free rule: __device__ globals)
__device__ unsigned long long g_hist[NBINS];   // 16 MB, packed count|mask
__device__ int                g_bins[NPIX];    // 64 MB per-pixel bin index
__device__ unsigned int       g_flag[NFLAGW];  // 256 KB bit table
__device__ double             g_sumf_in, g_suml_in, g_avg;
__device__ unsigned long long g_mask_total;
__device__ unsigned int       g_bar1, g_bar2;  // software grid barriers

// ---------------------------------------------------------------------------
// K0: clear histogram (vectorized) + scalars + barrier counters
// ---------------------------------------------------------------------------
__global__ void k_clear() {
    int i = blockIdx.x * blockDim.x + threadIdx.x;
    if (i < NBINS / 2) ((ulonglong2*)g_hist)[i] = make_ulonglong2(0ULL, 0ULL);
    if (i == 0) {
        g_sumf_in = 0.0; g_suml_in = 0.0; g_avg = 0.0;
        g_mask_total = 0ULL;
        g_bar1 = 0u; g_bar2 = 0u;
    }
}

// ---------------------------------------------------------------------------
// K1: histogram accumulate + per-pixel bin store. 4 pixels per thread.
// (exact R5/R8 version — proven best; atomic-issue floor, frozen)
// ---------------------------------------------------------------------------
__global__ void __launch_bounds__(256) k_hist(const int* __restrict__ img,
                                              const float* __restrict__ mask) {
    int t = blockIdx.x * blockDim.x + threadIdx.x;   // 0 .. NPIX/4-1
    if (t >= NPIX / 4) return;

    const int4* img4 = (const int4*)img;
    int4 a = img4[t * 3 + 0];
    int4 b = img4[t * 3 + 1];
    int4 c = img4[t * 3 + 2];
    float4 m = ((const float4*)mask)[t];

    int bin0 = ((a.x >> 1) << 14) | ((a.y >> 1) << 7) | (a.z >> 1);
    int bin1 = ((a.w >> 1) << 14) | ((b.x >> 1) << 7) | (b.y >> 1);
    int bin2 = ((b.z >> 1) << 14) | ((b.w >> 1) << 7) | (c.x >> 1);
    int bin3 = ((c.y >> 1) << 14) | ((c.z >> 1) << 7) | (c.w >> 1);

    unsigned long long v0 = (1ULL << COUNT_SHIFT) | (unsigned long long)(m.x * MASK_SCALE + 0.5f);
    unsigned long long v1 = (1ULL << COUNT_SHIFT) | (unsigned long long)(m.y * MASK_SCALE + 0.5f);
    unsigned long long v2 = (1ULL << COUNT_SHIFT) | (unsigned long long)(m.z * MASK_SCALE + 0.5f);
    unsigned long long v3 = (1ULL << COUNT_SHIFT) | (unsigned long long)(m.w * MASK_SCALE + 0.5f);

    atomicAdd(&g_hist[bin0], v0);
    atomicAdd(&g_hist[bin1], v1);
    atomicAdd(&g_hist[bin2], v2);
    atomicAdd(&g_hist[bin3], v3);

    ((int4*)g_bins)[t] = make_int4(bin0, bin1, bin2, bin3);
}

// ---------------------------------------------------------------------------
// K2 (fused): sums + log-ratio + flag table in one persistent kernel.
// Only change vs R8: Phase B uses __logf(l) - __logf(f) + C (no IEEE divide,
// half the MUFU ops). R4 evidence: __logf produced identical flip set.
// ---------------------------------------------------------------------------
__device__ __forceinline__ void grid_barrier(unsigned int* bar) {
    __syncthreads();
    if (threadIdx.x == 0) {
        __threadfence();
        atomicAdd(bar, 1u);
        while (*((volatile unsigned int*)bar) < FGRID) { }
        __threadfence();
    }
    __syncthreads();
}

__global__ void __launch_bounds__(1024) k_fused(const float* __restrict__ full_in,
                                                const float* __restrict__ lines_in) {
    int tid  = threadIdx.x;
    int lane = tid & 31;
    int wid  = tid >> 5;
    int W    = blockIdx.x * 32 + wid;    // global warp id, 0..4735

    // ---------------- Phase A: sums ----------------
    unsigned long long msum = 0ULL;
    float fsum = 0.0f, lsum = 0.0f;
    #pragma unroll
    for (int j = 0; j < CPT; j++) {
        int c = W + j * FWARPS;
        if (c < NCHUNK) {                 // warp-uniform guard
            int bin = c * 32 + lane;
            unsigned long long h = g_hist[bin];
            msum += (h & MASK40);
            fsum += full_in[bin];
            lsum += lines_in[bin];
        }
    }
    for (int o = 16; o > 0; o >>= 1) {
        msum += __shfl_down_sync(0xFFFFFFFFu, msum, o);
        fsum += __shfl_down_sync(0xFFFFFFFFu, fsum, o);
        lsum += __shfl_down_sync(0xFFFFFFFFu, lsum, o);
    }
    __shared__ unsigned long long sm[32];
    __shared__ float sf[32], sl[32];
    if (lane == 0) { sm[wid] = msum; sf[wid] = fsum; sl[wid] = lsum; }
    __syncthreads();
    if (wid == 0) {
        msum = sm[lane]; fsum = sf[lane]; lsum = sl[lane];
        for (int o = 16; o > 0; o >>= 1) {
            msum += __shfl_down_sync(0xFFFFFFFFu, msum, o);
            fsum += __shfl_down_sync(0xFFFFFFFFu, fsum, o);
            lsum += __shfl_down_sync(0xFFFFFFFFu, lsum, o);
        }
        if (lane == 0) {
            atomicAdd(&g_mask_total, msum);
            atomicAdd(&g_sumf_in, (double)fsum);
            atomicAdd(&g_suml_in, (double)lsum);
        }
    }
    grid_barrier(&g_bar1);

    // Derive scalars (identical doubles in every block)
    __shared__ float sC, sInvSl;
    if (tid == 0) {
        double sfd = *((volatile double*)&g_sumf_in) + (double)NPIX + (double)NBINS;
        double sld = *((volatile double*)&g_suml_in)
                   + (double)(*((volatile unsigned long long*)&g_mask_total)) * MASK_INV_SCALE_D
                   + (double)NBINS * 1e-10;
        sC = (float)(log(sfd) - log(sld));
        sInvSl = (float)(1.0 / sld);
    }
    __syncthreads();
    float C = sC, inv_sl = sInvSl;

    // ---------------- Phase B: log ratios (register-resident) + avg ----------
    float lr[CPT];
    float avg = 0.0f;
    #pragma unroll
    for (int j = 0; j < CPT; j++) {
        int c = W + j * FWARPS;
        if (c < NCHUNK) {                 // L2-hot re-reads
            int bin = c * 32 + lane;
            unsigned long long h = g_hist[bin];
            float cnt = (float)(h >> COUNT_SHIFT);
            float ms  = (float)(h & MASK40) * MASK_INV_SCALE;
            float f = full_in[bin] + cnt + 1.0f;
            float l = lines_in[bin] + ms + 1e-10f;
            float v = __logf(l) - __logf(f) + C;   // no divide, 2 MUFU -> effective 2 lg2
            lr[j] = v;
            avg += (l * inv_sl) * v;
        } else {
            lr[j] = 0.0f;
        }
    }
    for (int o = 16; o > 0; o >>= 1)
        avg += __shfl_down_sync(0xFFFFFFFFu, avg, o);
    __shared__ float sa[32];
    if (lane == 0) sa[wid] = avg;
    __syncthreads();
    if (wid == 0) {
        avg = sa[lane];
        for (int o = 16; o > 0; o >>= 1)
            avg += __shfl_down_sync(0xFFFFFFFFu, avg, o);
        if (lane == 0) atomicAdd(&g_avg, (double)avg);
    }
    grid_barrier(&g_bar2);

    // ---------------- Phase C: flag bits via ballot ----------------
    float avgf = (float)(*((volatile double*)&g_avg));
    #pragma unroll
    for (int j = 0; j < CPT; j++) {
        int c = W + j * FWARPS;
        if (c < NCHUNK) {                 // warp-uniform: full-warp ballot
            unsigned int m = __ballot_sync(0xFFFFFFFFu, lr[j] > avgf);
            if (lane == 0) g_flag[c] = m;
        }
    }
}

// ---------------------------------------------------------------------------
// K4: gather. 224KB of the bit table in smem (covers 87.5% of bins), rest via
// L2. Persistent: 148 blocks x 1024 threads. (exact R8 version — proven best)
// ---------------------------------------------------------------------------
__global__ void __launch_bounds__(1024) k_out(float* __restrict__ out) {
    extern __shared__ unsigned int s_flag[];
    for (int i = threadIdx.x; i < SMEM_WORDS; i += 1024)
        s_flag[i] = g_flag[i];
    __syncthreads();

    int stride = gridDim.x * 1024;
    for (int t = blockIdx.x * 1024 + threadIdx.x; t < NPIX / 4; t += stride) {
        int4 bb = ((const int4*)g_bins)[t];
        float4 o;
        {
            int w = bb.x >> 5, bit = bb.x & 31;
            unsigned int word = (w < SMEM_WORDS) ? s_flag[w] : __ldg(&g_flag[w]);
            o.x = (float)((word >> bit) & 1u);
        }
        {
            int w = bb.y >> 5, bit = bb.y & 31;
            unsigned int word = (w < SMEM_WORDS) ? s_flag[w] : __ldg(&g_flag[w]);
            o.y = (float)((word >> bit) & 1u);
        }
        {
            int w = bb.z >> 5, bit = bb.z & 31;
            unsigned int word = (w < SMEM_WORDS) ? s_flag[w] : __ldg(&g_flag[w]);
            o.z = (float)((word >> bit) & 1u);
        }
        {
            int w = bb.w >> 5, bit = bb.w & 31;
            unsigned int word = (w < SMEM_WORDS) ? s_flag[w] : __ldg(&g_flag[w]);
            o.w = (float)((word >> bit) & 1u);
        }
        ((float4*)out)[t] = o;
    }
}

extern "C" void kernel_launch(void* const* d_in, const int* in_sizes, int n_in,
                              void* d_out, int out_size) {
    const int*   img      = (const int*)d_in[0];
    const float* mask     = (const float*)d_in[1];
    const float* full_in  = (const float*)d_in[2];
    const float* lines_in = (const float*)d_in[3];
    float* out            = (float*)d_out;

    // Idempotent opt-in for 224KB dynamic smem (non-stream call; capture-safe).
    cudaFuncSetAttribute(k_out, cudaFuncAttributeMaxDynamicSharedMemorySize, SMEM_BYTES);

    k_clear<<<(NBINS / 2) / 256, 256>>>();
    k_hist <<<(NPIX / 4) / 256, 256>>>(img, mask);
    k_fused<<<FGRID, 1024>>>(full_in, lines_in);
    k_out  <<<148, 1024, SMEM_BYTES>>>(out);
}